// round 10
// baseline (speedup 1.0000x reference)
#include <cuda_runtime.h>
#include <cuda_bf16.h>

#define NN 1024
#define HH 96
#define EE 16384
#define TJ 64
#define BI 8

// ---------------- device scratch (no allocation allowed) ----------------
__device__ float g_xA[NN * HH];
__device__ float g_xB[NN * HH];
__device__ float g_m[NN * HH];
__device__ float g_hip[NN * HH];   // 0.5*(x@Wa1[:, :H].T + ba1)
__device__ float g_hjp[NN * HH];   // 0.5*(x@Wa1[:, H:].T)
__device__ int   g_off[NN + 1];
__device__ int   g_csr[EE];
// transposed weights (coalesced loads)
__device__ float g_TWih[HH * 288]; // [k][gate*96+h]
__device__ float g_TWhh[HH * 288];
__device__ float g_TA[HH * 192];
__device__ float g_TO1[HH * HH];
__device__ float g_TO2[HH * HH];

__device__ __forceinline__ float sigf(float v) {
    return __fdividef(1.0f, 1.0f + __expf(-v));
}
__device__ __forceinline__ float leakyf(float v) {
    return v >= 0.0f ? v : 0.01f * v;
}
__device__ __forceinline__ float tanhfast(float v) {
    float y;
    asm("tanh.approx.f32 %0, %1;" : "=f"(y) : "f"(v));
    return y;
}

// ---------------- K0: weight transpose + input projection ---------------
__global__ void k_setup(const float* __restrict__ x,
                        const float* __restrict__ Wi, const float* __restrict__ bi,
                        const float* __restrict__ Wih, const float* __restrict__ Whh,
                        const float* __restrict__ Wa1,
                        const float* __restrict__ Wo1, const float* __restrict__ Wo2) {
    int b = blockIdx.x, t = threadIdx.x;
    if (b < HH) {
        int k = b;
        g_TWih[k * 288 + t] = Wih[t * HH + k];
        g_TWhh[k * 288 + t] = Whh[t * HH + k];
        if (t < 192)
            g_TA[k * 192 + t] = (t < HH) ? Wa1[t * 192 + k]
                                         : Wa1[(t - HH) * 192 + HH + k];
        if (t < HH) {
            g_TO1[k * HH + t] = Wo1[t * HH + k];
            g_TO2[k * HH + t] = Wo2[t * HH + k];
        }
    } else {
        int rr = t / HH, h = t - rr * HH;
        int i = (b - HH) * 3 + rr;
        if (i < NN) {
            float a = bi[h];
#pragma unroll
            for (int c = 0; c < 9; c++) a = fmaf(x[i * 10 + c], Wi[h * 9 + c], a);
            g_xA[i * HH + h] = leakyf(a);
        }
    }
}

// ---------------- K1: degree count + scan + CSR fill, one block ---------
__global__ void k_scanfill(const int* __restrict__ ei) {
    __shared__ int cnt[NN];
    __shared__ int cur[NN];
    __shared__ int wsum[32];
    int t = threadIdx.x, lane = t & 31, wid = t >> 5;
    cnt[t] = 0;
    __syncthreads();
    for (int e = t; e < EE; e += NN) atomicAdd(&cnt[ei[EE + e]], 1);
    __syncthreads();
    int d = cnt[t], v = d;
#pragma unroll
    for (int o = 1; o < 32; o <<= 1) {
        int u = __shfl_up_sync(0xffffffffu, v, o);
        if (lane >= o) v += u;
    }
    if (lane == 31) wsum[wid] = v;
    __syncthreads();
    if (wid == 0) {
        int s = wsum[lane];
#pragma unroll
        for (int o = 1; o < 32; o <<= 1) {
            int u = __shfl_up_sync(0xffffffffu, s, o);
            if (lane >= o) s += u;
        }
        wsum[lane] = s;
    }
    __syncthreads();
    int incl = v + (wid ? wsum[wid - 1] : 0);
    g_off[t + 1] = incl;
    if (t == 0) g_off[0] = 0;
    cur[t] = incl - d;
    __syncthreads();
    for (int e = t; e < EE; e += NN) {
        int s = ei[e], tg = ei[EE + e];
        int p = atomicAdd(&cur[tg], 1);
        g_csr[p] = s;
    }
}

// ---------------- K2: m = x @ W_ggc, 4 rows, 288 thr (3 k-segments) -----
__global__ void __launch_bounds__(288) k_mggc(int sel, const float* __restrict__ Wg) {
    const float* xc = sel ? g_xB : g_xA;
    int i0 = blockIdx.x * 4, t = threadIdx.x;
    int h = t % HH, g = t / HH;            // g in 0..2 -> k in [g*32, g*32+32)
    __shared__ float xs[4][HH];
    __shared__ float part[3][4][HH];
    for (int f = t; f < 4 * HH; f += 288) {
        int r = f / HH, h2 = f - r * HH;
        xs[r][h2] = xc[(i0 + r) * HH + h2];
    }
    __syncthreads();
    float a[4] = {0.f, 0.f, 0.f, 0.f};
    int k0 = g * 32;
#pragma unroll 8
    for (int kk = 0; kk < 32; kk++) {
        int k = k0 + kk;
        float wv = Wg[k * HH + h];
#pragma unroll
        for (int r = 0; r < 4; r++) a[r] = fmaf(xs[r][k], wv, a[r]);
    }
#pragma unroll
    for (int r = 0; r < 4; r++) part[g][r][h] = a[r];
    __syncthreads();
    for (int f = t; f < 4 * HH; f += 288) {
        int r = f / HH, h2 = f - r * HH;
        g_m[(i0 + r) * HH + h2] = part[0][r][h2] + part[1][r][h2] + part[2][r][h2];
    }
}

// ---------------- K3: GRU + projections, 4 rows, 288 threads ------------
// thread t owns gate-row t (g = t/96 in {r,z,n}, h = t%96)
__global__ void __launch_bounds__(288) k_gruproj(int sel,
                          const float* __restrict__ bih, const float* __restrict__ bhh,
                          const float* __restrict__ ba1) {
    float* xc = sel ? g_xB : g_xA;
    float* xn = sel ? g_xA : g_xB;
    int i0 = blockIdx.x * 4, t = threadIdx.x;
    int h = t % HH, g = t / HH;
    __shared__ float ag[4][HH], xs[4][HH];
    __shared__ float gA[4][288];   // r,z: combined sums; n: inn part
    __shared__ float gN[4][HH];    // n: hn part, then reused as xnew
    // gather + load x (384 tasks over 288 threads)
    for (int f = t; f < 4 * HH; f += 288) {
        int r = f / HH, h2 = f - r * HH;
        int row = i0 + r;
        int beg = g_off[row], end = g_off[row + 1];
        float s = 0.0f;
        for (int e = beg; e < end; e++) s += g_m[g_csr[e] * HH + h2];
        int d = end - beg;
        ag[r][h2] = __fdividef(s, (float)(d > 1 ? d : 1));
        xs[r][h2] = xc[row * HH + h2];
    }
    __syncthreads();
    float acc_i[4] = {0.f, 0.f, 0.f, 0.f};
    float acc_h[4] = {0.f, 0.f, 0.f, 0.f};
#pragma unroll 4
    for (int k = 0; k < HH; k++) {
        float wi = g_TWih[k * 288 + t];
        float wh = g_TWhh[k * 288 + t];
#pragma unroll
        for (int r = 0; r < 4; r++) {
            acc_i[r] = fmaf(ag[r][k], wi, acc_i[r]);
            acc_h[r] = fmaf(xs[r][k], wh, acc_h[r]);
        }
    }
    if (g < 2) {
        float bb = bih[g * HH + h] + bhh[g * HH + h];
#pragma unroll
        for (int r = 0; r < 4; r++) gA[r][t] = acc_i[r] + acc_h[r] + bb;
    } else {
        float bi_n = bih[2 * HH + h], bh_n = bhh[2 * HH + h];
#pragma unroll
        for (int r = 0; r < 4; r++) {
            gA[r][t] = acc_i[r] + bi_n;
            gN[r][h] = acc_h[r] + bh_n;
        }
    }
    __syncthreads();
    // GRU nonlinearity (384 tasks); write new x to gN and to global
    for (int f = t; f < 4 * HH; f += 288) {
        int r = f / HH, h2 = f - r * HH;
        float rr = sigf(gA[r][h2]);
        float zz = sigf(gA[r][HH + h2]);
        float n = tanhf(gA[r][2 * HH + h2] + rr * gN[r][h2]);
        float xv = (1.0f - zz) * n + zz * xs[r][h2];
        int row = i0 + r;
        xc[row * HH + h2] = xv;
        xn[row * HH + h2] = 0.0f;     // accumulation target for k_att
        gA[r][h2] = xv;               // staged new x for projections
    }
    __syncthreads();
    // projections on new x: 768 tasks (r, c<192)
    for (int f = t; f < 4 * 192; f += 288) {
        int r = f / 192, c = f - r * 192;
        float acc = (c < HH) ? ba1[c] : 0.0f;
#pragma unroll 4
        for (int k = 0; k < HH; k++) acc = fmaf(gA[r][k], g_TA[k * 192 + c], acc);
        float v = 0.5f * acc;
        int row = i0 + r;
        if (c < HH) g_hip[row * HH + c] = v;
        else        g_hjp[row * HH + c - HH] = v;
    }
}

// ---------------- K4: attention + x = coeffs @ x ------------------------
__global__ void __launch_bounds__(256) k_att(int sel,
                                             const int* __restrict__ adj,
                                             const float* __restrict__ Wa2,
                                             const float* __restrict__ ba2) {
    const float* xc = sel ? g_xB : g_xA;
    float* xn = sel ? g_xA : g_xB;
    const int rg = blockIdx.x >> 1;
    const int jbase = (blockIdx.x & 1) * (NN / 2);
    const int i0 = rg * BI;
    int tid = threadIdx.x, lane = tid & 31, w = tid >> 5;
    __shared__ float hi_s[BI][HH];
    __shared__ float w_s[HH];
    __shared__ float tile[TJ][HH + 1];
    __shared__ float c2[TJ][BI];
    __shared__ float bs_s;

    if (tid < HH) w_s[tid] = 0.5f * Wa2[tid];
    for (int f = tid; f < BI * HH; f += 256) {
        int il = f / HH, k = f - il * HH;
        hi_s[il][k] = g_hip[(i0 + il) * HH + k];
    }
    __syncthreads();
    if (tid == 0) {
        float s = ba2[0];
        for (int k = 0; k < HH; k++) s += w_s[k];
        bs_s = s;
    }
    __syncthreads();

    const int jl = tid >> 2, q = tid & 3;
    float wr[24];
#pragma unroll
    for (int s = 0; s < 24; s++) wr[s] = w_s[q * 24 + s];
    const float base = bs_s;

    float a0[BI], a1[BI], a2[BI];
#pragma unroll
    for (int il = 0; il < BI; il++) { a0[il] = 0.f; a1[il] = 0.f; a2[il] = 0.f; }

    for (int jt = 0; jt < NN / 2; jt += TJ) {
        for (int f = tid; f < TJ * HH; f += 256) {
            int r = f / HH, k = f - r * HH;
            tile[r][k] = g_hjp[(jbase + jt) * HH + f];
        }
        __syncthreads();
        float p[BI];
#pragma unroll
        for (int il = 0; il < BI; il++) p[il] = 0.0f;
#pragma unroll 4
        for (int s = 0; s < 24; s++) {
            int k = q * 24 + s;
            float tj = tile[jl][k];
            float ws = wr[s];
#pragma unroll
            for (int il = 0; il < BI; il++)
                p[il] = fmaf(ws, tanhfast(hi_s[il][k] + tj), p[il]);
        }
#pragma unroll
        for (int il = 0; il < BI; il++) {
            p[il] += __shfl_xor_sync(0xffffffffu, p[il], 1);
            p[il] += __shfl_xor_sync(0xffffffffu, p[il], 2);
        }
        if (q == 0) {
            int j = jbase + jt + jl;
#pragma unroll
            for (int il = 0; il < BI; il++) {
                int a = adj[(long)(i0 + il) * NN + j];
                float sv = p[il] + base;
                c2[jl][il] = a ? fmaf(0.5f, tanhfast(0.5f * sv), 0.5f) : 0.0f;
            }
        }
        __syncthreads();
        for (int f = tid; f < TJ * HH; f += 256) {
            int r = f / HH, k = f - r * HH;
            tile[r][k] = xc[(jbase + jt) * HH + f];
        }
        __syncthreads();
#pragma unroll
        for (int u = 0; u < 8; u++) {
            int jj = w * 8 + u;
            float t0 = tile[jj][lane];
            float t1 = tile[jj][lane + 32];
            float t2 = tile[jj][lane + 64];
#pragma unroll
            for (int il = 0; il < BI; il++) {
                float c = c2[jj][il];
                a0[il] = fmaf(c, t0, a0[il]);
                a1[il] = fmaf(c, t1, a1[il]);
                a2[il] = fmaf(c, t2, a2[il]);
            }
        }
        __syncthreads();
    }
    float* sa = &tile[0][0];
#pragma unroll
    for (int il = 0; il < BI; il++) {
        sa[(w * BI + il) * HH + lane] = a0[il];
        sa[(w * BI + il) * HH + lane + 32] = a1[il];
        sa[(w * BI + il) * HH + lane + 64] = a2[il];
    }
    __syncthreads();
    for (int f = tid; f < BI * HH; f += 256) {
        int il = f / HH, h = f - il * HH;
        float s = 0.0f;
#pragma unroll
        for (int ww = 0; ww < 8; ww++) s += sa[(ww * BI + il) * HH + h];
        atomicAdd(&xn[(i0 + il) * HH + h], s);
    }
}

// ---------------- K5: output head, 4 rows per block ---------------------
__global__ void k_out(int sel,
                      const float* __restrict__ bo1, const float* __restrict__ bo2,
                      const float* __restrict__ Wp1, const float* __restrict__ bp1,
                      const float* __restrict__ Wp2, const float* __restrict__ bp2,
                      float* __restrict__ out) {
    const float* xc = sel ? g_xB : g_xA;
    int i0 = blockIdx.x * 4, h = threadIdx.x, lane = h & 31, w = h >> 5;
    __shared__ float xs[4][HH], y1[4][HH], y2[4][HH];
#pragma unroll
    for (int r = 0; r < 4; r++) xs[r][h] = xc[(i0 + r) * HH + h];
    __syncthreads();
    {
        float bb = bo1[h];
        float a[4] = {bb, bb, bb, bb};
#pragma unroll 4
        for (int k = 0; k < HH; k++) {
            float wv = g_TO1[k * HH + h];
#pragma unroll
            for (int r = 0; r < 4; r++) a[r] = fmaf(xs[r][k], wv, a[r]);
        }
#pragma unroll
        for (int r = 0; r < 4; r++) y1[r][h] = leakyf(a[r]);
    }
    __syncthreads();
    {
        float bb = bo2[h];
        float a[4] = {bb, bb, bb, bb};
#pragma unroll 4
        for (int k = 0; k < HH; k++) {
            float wv = g_TO2[k * HH + h];
#pragma unroll
            for (int r = 0; r < 4; r++) a[r] = fmaf(y1[r][k], wv, a[r]);
        }
#pragma unroll
        for (int r = 0; r < 4; r++) y2[r][h] = leakyf(a[r]);
    }
    __syncthreads();
    if (w < 2) {
        const float* Wp = (w == 0) ? Wp1 : Wp2;
        float bp = (w == 0) ? bp1[0] : bp2[0];
#pragma unroll
        for (int r = 0; r < 4; r++) {
            float p = y2[r][lane] * Wp[lane] + y2[r][lane + 32] * Wp[lane + 32]
                    + y2[r][lane + 64] * Wp[lane + 64];
#pragma unroll
            for (int o = 16; o > 0; o >>= 1) p += __shfl_xor_sync(0xffffffffu, p, o);
            if (lane == 0) out[w * NN + i0 + r] = sigf(p + bp);
        }
    }
}

// ---------------- launch ----------------
extern "C" void kernel_launch(void* const* d_in, const int* in_sizes, int n_in,
                              void* d_out, int out_size) {
    const float* x      = (const float*)d_in[0];
    const int*   ei     = (const int*)d_in[1];   // int32 (JAX x64 disabled)
    const int*   adj    = (const int*)d_in[2];
    const float* W_init = (const float*)d_in[3];
    const float* b_init = (const float*)d_in[4];
    const float* W_ggc  = (const float*)d_in[5];
    const float* W_ih   = (const float*)d_in[6];
    const float* W_hh   = (const float*)d_in[7];
    const float* b_ih   = (const float*)d_in[8];
    const float* b_hh   = (const float*)d_in[9];
    const float* Wa1    = (const float*)d_in[10];
    const float* ba1    = (const float*)d_in[11];
    const float* Wa2    = (const float*)d_in[12];
    const float* ba2    = (const float*)d_in[13];
    const float* Wo1    = (const float*)d_in[14];
    const float* bo1    = (const float*)d_in[15];
    const float* Wo2    = (const float*)d_in[16];
    const float* bo2    = (const float*)d_in[17];
    const float* Wp1    = (const float*)d_in[18];
    const float* bp1    = (const float*)d_in[19];
    const float* Wp2    = (const float*)d_in[20];
    const float* bp2    = (const float*)d_in[21];
    float* out = (float*)d_out;

    k_setup<<<96 + 342, 288>>>(x, W_init, b_init, W_ih, W_hh, Wa1, Wo1, Wo2);
    k_scanfill<<<1, NN>>>(ei);

    for (int t = 0; t < 2; t++) {
        int sel = t & 1;   // x in A when t==0, in B when t==1
        k_mggc<<<NN / 4, 288>>>(sel, W_ggc);
        k_gruproj<<<NN / 4, 288>>>(sel, b_ih, b_hh, ba1);
        k_att<<<NN / BI * 2, 256>>>(sel, adj, Wa2, ba2);
    }
    k_out<<<NN / 4, HH>>>(0, bo1, bo2, Wp1, bp1, Wp2, bp2, out);
}